// round 11
// baseline (speedup 1.0000x reference)
#include <cuda_runtime.h>
#include <math.h>

#define CC   16
#define DIMN 16
#define LL   6

typedef unsigned long long u64;

// ---------------- device-global precomputed params ----------------
// Deltas, cp-INNERMOST layout: entry (l, j, cp) holds dims {2j,2j+1} for c0=2cp, c1=2cp+1:
//   .x = ( -D_l[c0][2j],   -D_l[c1][2j]   )
//   .y = ( -D_l[c0][2j+1], -D_l[c1][2j+1] )   where -D_0 = -z0_0, -D_l = z0_{l-1}-z0_l
__device__ ulonglong2 g_negD2[LL * 8 * 8];   // index l*64 + j*8 + cp
__device__ ulonglong2 g_m52[8 * 8];          // (z0_5 - mean), index j*8 + cp
__device__ ulonglong2 g_parab[LL * 8];       // {(a_c0,a_c1), (b_c0,b_c1)}, index l*8+cp
__device__ u64        g_parc[LL * 8];        // (a*b) pair
__device__ u64        g_hld2[8];             // half_logdet pair
__device__ float      g_hld[CC];
__device__ float      g_Linv[CC * DIMN * DIMN];
__device__ int        g_ident;

// ---------------- f32x2 packed helpers (sm_103a) -------------------
__device__ __forceinline__ u64 pk2(float lo, float hi) {
    u64 r; asm("mov.b64 %0, {%1, %2};" : "=l"(r) : "f"(lo), "f"(hi)); return r;
}
__device__ __forceinline__ void up2(float& lo, float& hi, u64 v) {
    asm("mov.b64 {%0, %1}, %2;" : "=f"(lo), "=f"(hi) : "l"(v));
}
__device__ __forceinline__ u64 ffma2(u64 a, u64 b, u64 c) {
    u64 d; asm("fma.rn.f32x2 %0, %1, %2, %3;" : "=l"(d) : "l"(a), "l"(b), "l"(c)); return d;
}
__device__ __forceinline__ u64 add2(u64 a, u64 b) {
    u64 d; asm("add.rn.f32x2 %0, %1, %2;" : "=l"(d) : "l"(a), "l"(b)); return d;
}
__device__ __forceinline__ u64 mul2(u64 a, u64 b) {
    u64 d; asm("mul.rn.f32x2 %0, %1, %2;" : "=l"(d) : "l"(a), "l"(b)); return d;
}
__device__ __forceinline__ float fast_sqrt(float x) {
    float r; asm("sqrt.approx.f32 %0, %1;" : "=f"(r) : "f"(x)); return r;
}
__device__ __forceinline__ float fast_rcp(float x) {
    float r; asm("rcp.approx.f32 %0, %1;" : "=f"(r) : "f"(x)); return r;
}

// per-layer scalar tail: (e0+e1) -> r -> h -> f1,f2; updates P1,P2; returns f1 pair
__device__ __forceinline__ u64 tail_step(u64 e0, u64 e1, ulonglong2 pab, u64 abp,
                                         u64& P1p, u64& P2p) {
    const u64 ONE2 = pk2(1.0f, 1.0f);
    u64 r2p = add2(e0, e1);
    float rA, rB; up2(rA, rB, r2p);
    u64 rp = pk2(fast_sqrt(rA), fast_sqrt(rB));
    u64 up = add2(pab.x, rp);                 // alpha + r
    float uA, uB; up2(uA, uB, up);
    u64 hp = pk2(fast_rcp(uA), fast_rcp(uB));
    u64 f1p = ffma2(pab.y, hp, ONE2);         // 1 + beta*h
    u64 f2p = ffma2(abp, mul2(hp, hp), ONE2); // 1 + alpha*beta*h^2
    P1p = mul2(P1p, f1p);
    P2p = mul2(P2p, f2p);
    return f1p;
}

// ---------------- setup kernel ----------------
__global__ void setup_kernel(const float* __restrict__ la, const float* __restrict__ be,
                             const float* __restrict__ z0, const float* __restrict__ mean,
                             const float* __restrict__ cov) {
    __shared__ int s_bad;
    int t = threadIdx.x;
    if (t == 0) s_bad = 0;
    __syncthreads();

    // packed params per (layer, c-pair)
    for (int i = t; i < LL * 8; i += 256) {
        int l = i / 8, cp = i % 8;
        int c0 = 2 * cp, c1 = c0 + 1;
        float a0 = expf(la[l * CC + c0]), a1 = expf(la[l * CC + c1]);
        float b0 = be[l * CC + c0],       b1 = be[l * CC + c1];
        ulonglong2 v; v.x = pk2(a0, a1); v.y = pk2(b0, b1);
        g_parab[i] = v;
        g_parc[i]  = pk2(a0 * b0, a1 * b1);
    }
    // layer deltas, cp-innermost: index l*64 + j*8 + cp
    for (int i = t; i < LL * 8 * 8; i += 256) {
        int l = i / 64, rem = i % 64, j = rem / 8, cp = rem % 8;
        int c0 = 2 * cp, c1 = c0 + 1;
        int b0 = (l * CC + c0) * DIMN + 2 * j;
        int b1 = (l * CC + c1) * DIMN + 2 * j;
        float x0 = -z0[b0], y0 = -z0[b0 + 1];
        float x1 = -z0[b1], y1 = -z0[b1 + 1];
        if (l > 0) {
            int p0 = ((l - 1) * CC + c0) * DIMN + 2 * j;
            int p1 = ((l - 1) * CC + c1) * DIMN + 2 * j;
            x0 += z0[p0]; y0 += z0[p0 + 1];
            x1 += z0[p1]; y1 += z0[p1 + 1];
        }
        ulonglong2 v; v.x = pk2(x0, x1); v.y = pk2(y0, y1);
        g_negD2[i] = v;
    }
    // final offset: z0_5 - mean, cp-innermost: index j*8 + cp
    for (int i = t; i < 8 * 8; i += 256) {
        int j = i / 8, cp = i % 8;
        int c0 = 2 * cp, c1 = c0 + 1;
        int b0 = (5 * CC + c0) * DIMN + 2 * j;
        int b1 = (5 * CC + c1) * DIMN + 2 * j;
        int m0 = c0 * DIMN + 2 * j, m1 = c1 * DIMN + 2 * j;
        ulonglong2 v;
        v.x = pk2(z0[b0]     - mean[m0],     z0[b1]     - mean[m1]);
        v.y = pk2(z0[b0 + 1] - mean[m0 + 1], z0[b1 + 1] - mean[m1 + 1]);
        g_m52[i] = v;
    }

    int bad = 0;
    for (int i = t; i < CC * DIMN * DIMN; i += 256) {
        float e = (((i % (DIMN * DIMN)) % (DIMN + 1)) == 0) ? 1.0f : 0.0f;
        if (cov[i] != e) bad = 1;
    }
    if (bad) atomicOr(&s_bad, 1);
    __syncthreads();
    int id = (s_bad == 0) ? 1 : 0;
    if (t == 0) g_ident = id;

    int c = t;
    if (c < CC) {
        if (id) {
            g_hld[c] = 0.0f;
        } else {
            // general Cholesky + triangular inverse (cold path)
            float Lm[DIMN][DIMN];
            const float* A = cov + c * DIMN * DIMN;
            #pragma unroll 1
            for (int j = 0; j < DIMN; j++) {
                float s = A[j * DIMN + j];
                #pragma unroll 1
                for (int k = 0; k < j; k++) s -= Lm[j][k] * Lm[j][k];
                float d = sqrtf(s);
                Lm[j][j] = d;
                float inv = 1.0f / d;
                #pragma unroll 1
                for (int i = j + 1; i < DIMN; i++) {
                    float s2 = A[i * DIMN + j];
                    #pragma unroll 1
                    for (int k = 0; k < j; k++) s2 -= Lm[i][k] * Lm[j][k];
                    Lm[i][j] = s2 * inv;
                }
            }
            float hld = 0.0f;
            #pragma unroll 1
            for (int j = 0; j < DIMN; j++) hld += logf(Lm[j][j]);
            g_hld[c] = hld;

            float Li[DIMN][DIMN];
            #pragma unroll 1
            for (int j = 0; j < DIMN; j++) {
                for (int i = 0; i < DIMN; i++) Li[i][j] = 0.0f;
                Li[j][j] = 1.0f / Lm[j][j];
                #pragma unroll 1
                for (int i = j + 1; i < DIMN; i++) {
                    float s3 = 0.0f;
                    #pragma unroll 1
                    for (int k = j; k < i; k++) s3 += Lm[i][k] * Li[k][j];
                    Li[i][j] = -s3 / Lm[i][i];
                }
            }
            for (int i = 0; i < DIMN; i++)
                for (int j = 0; j < DIMN; j++)
                    g_Linv[(c * DIMN + i) * DIMN + j] = Li[i][j];
        }
    }
    __syncthreads();
    if (t < 8) g_hld2[t] = pk2(g_hld[2 * t], g_hld[2 * t + 1]);
}

// ---------------- main density kernel: 1 thread per point, 2 cp-chains interleaved ----------------
__global__ void __launch_bounds__(128, 4)
density_kernel(const float* __restrict__ z, float* __restrict__ out, int N)
{
    __shared__ ulonglong2 s_negD[LL * 8 * 8];     // 6 KB, index l*64 + j*8 + cp
    __shared__ ulonglong2 s_m5[8 * 8];            // 1 KB, index j*8 + cp
    __shared__ ulonglong2 s_parab[LL * 8];        // 768 B
    __shared__ u64        s_parc[LL * 8];         // 384 B
    __shared__ u64        s_hld2[8];

    int t = threadIdx.x;
    for (int i = t; i < LL * 8 * 8; i += 128) s_negD[i] = g_negD2[i];
    if (t < 8 * 8) s_m5[t] = g_m52[t];
    if (t < LL * 8) { s_parab[t] = g_parab[t]; s_parc[t] = g_parc[t]; }
    if (t < 8) s_hld2[t] = g_hld2[t];
    int ident = g_ident;
    __syncthreads();

    int n = blockIdx.x * 128 + t;
    if (n >= N) return;

    // z row as 16 scalar registers (pk2 broadcast on use in layer 0)
    const float4* zr = (const float4*)(z + (size_t)n * DIMN);
    float4 q0 = zr[0], q1 = zr[1], q2 = zr[2], q3 = zr[3];
    float zf[16] = { q0.x, q0.y, q0.z, q0.w, q1.x, q1.y, q1.z, q1.w,
                     q2.x, q2.y, q2.z, q2.w, q3.x, q3.y, q3.z, q3.w };

    const float HALF_DIM_LOG2PI = 14.7030165f;   // 0.5 * 16 * log(2*pi)
    const u64 ONE2 = pk2(1.0f, 1.0f);

    #pragma unroll 1
    for (int cpi = 0; cpi < 4; cpi++) {
        const int cpA = cpi, cpB = cpi + 4;
        const ulonglong2* dpA = &s_negD[cpA];
        const ulonglong2* dpB = &s_negD[cpB];

        u64 sA[16], sB[16];
        u64 e0A = 0ull, e1A = 0ull, e0B = 0ull, e1B = 0ull;

        // ---- layer 0: s = z - z0_0, both chains ----
        #pragma unroll
        for (int j = 0; j < 8; j++) {
            ulonglong2 ddA = dpA[j * 8];
            ulonglong2 ddB = dpB[j * 8];
            u64 za = pk2(zf[2 * j],     zf[2 * j]);
            u64 zb = pk2(zf[2 * j + 1], zf[2 * j + 1]);
            sA[2 * j]     = add2(za, ddA.x);
            sA[2 * j + 1] = add2(zb, ddA.y);
            sB[2 * j]     = add2(za, ddB.x);
            sB[2 * j + 1] = add2(zb, ddB.y);
            e0A = ffma2(sA[2 * j],     sA[2 * j],     e0A);
            e1A = ffma2(sA[2 * j + 1], sA[2 * j + 1], e1A);
            e0B = ffma2(sB[2 * j],     sB[2 * j],     e0B);
            e1B = ffma2(sB[2 * j + 1], sB[2 * j + 1], e1B);
        }

        u64 P1A = ONE2, P2A = ONE2, P1B = ONE2, P2B = ONE2, f1A, f1B;

        // ---- layers 1..5: prefetch both chains' deltas, run both MUFU tails, update ----
        #pragma unroll
        for (int l = 1; l < LL; l++) {
            const ulonglong2* dlA = dpA + l * 64;
            const ulonglong2* dlB = dpB + l * 64;
            // prefetch half of each chain's next-layer deltas; tails below cover latency
            ulonglong2 a0 = dlA[0], a1 = dlA[8], a2 = dlA[16], a3 = dlA[24];
            ulonglong2 b0 = dlB[0], b1 = dlB[8], b2 = dlB[16], b3 = dlB[24];
            ulonglong2 pabA = s_parab[(l - 1) * 8 + cpA];
            ulonglong2 pabB = s_parab[(l - 1) * 8 + cpB];
            u64 abpA = s_parc[(l - 1) * 8 + cpA];
            u64 abpB = s_parc[(l - 1) * 8 + cpB];

            f1A = tail_step(e0A, e1A, pabA, abpA, P1A, P2A);
            f1B = tail_step(e0B, e1B, pabB, abpB, P1B, P2B);

            e0A = 0ull; e1A = 0ull; e0B = 0ull; e1B = 0ull;
            sA[0] = ffma2(f1A, sA[0], a0.x); sA[1] = ffma2(f1A, sA[1], a0.y);
            sB[0] = ffma2(f1B, sB[0], b0.x); sB[1] = ffma2(f1B, sB[1], b0.y);
            e0A = ffma2(sA[0], sA[0], e0A);  e1A = ffma2(sA[1], sA[1], e1A);
            e0B = ffma2(sB[0], sB[0], e0B);  e1B = ffma2(sB[1], sB[1], e1B);
            sA[2] = ffma2(f1A, sA[2], a1.x); sA[3] = ffma2(f1A, sA[3], a1.y);
            sB[2] = ffma2(f1B, sB[2], b1.x); sB[3] = ffma2(f1B, sB[3], b1.y);
            e0A = ffma2(sA[2], sA[2], e0A);  e1A = ffma2(sA[3], sA[3], e1A);
            e0B = ffma2(sB[2], sB[2], e0B);  e1B = ffma2(sB[3], sB[3], e1B);
            sA[4] = ffma2(f1A, sA[4], a2.x); sA[5] = ffma2(f1A, sA[5], a2.y);
            sB[4] = ffma2(f1B, sB[4], b2.x); sB[5] = ffma2(f1B, sB[5], b2.y);
            e0A = ffma2(sA[4], sA[4], e0A);  e1A = ffma2(sA[5], sA[5], e1A);
            e0B = ffma2(sB[4], sB[4], e0B);  e1B = ffma2(sB[5], sB[5], e1B);
            sA[6] = ffma2(f1A, sA[6], a3.x); sA[7] = ffma2(f1A, sA[7], a3.y);
            sB[6] = ffma2(f1B, sB[6], b3.x); sB[7] = ffma2(f1B, sB[7], b3.y);
            e0A = ffma2(sA[6], sA[6], e0A);  e1A = ffma2(sA[7], sA[7], e1A);
            e0B = ffma2(sB[6], sB[6], e0B);  e1B = ffma2(sB[7], sB[7], e1B);
            #pragma unroll
            for (int j = 4; j < 8; j++) {
                ulonglong2 ddA = dlA[j * 8];
                ulonglong2 ddB = dlB[j * 8];
                sA[2 * j]     = ffma2(f1A, sA[2 * j],     ddA.x);
                sA[2 * j + 1] = ffma2(f1A, sA[2 * j + 1], ddA.y);
                sB[2 * j]     = ffma2(f1B, sB[2 * j],     ddB.x);
                sB[2 * j + 1] = ffma2(f1B, sB[2 * j + 1], ddB.y);
                e0A = ffma2(sA[2 * j],     sA[2 * j],     e0A);
                e1A = ffma2(sA[2 * j + 1], sA[2 * j + 1], e1A);
                e0B = ffma2(sB[2 * j],     sB[2 * j],     e0B);
                e1B = ffma2(sB[2 * j + 1], sB[2 * j + 1], e1B);
            }
        }

        // ---- final: tails, then q = |f1*s + m5|^2 for both chains ----
        const ulonglong2* mpA = &s_m5[cpA];
        const ulonglong2* mpB = &s_m5[cpB];
        ulonglong2 pab5A = s_parab[5 * 8 + cpA];
        ulonglong2 pab5B = s_parab[5 * 8 + cpB];
        u64 abp5A = s_parc[5 * 8 + cpA];
        u64 abp5B = s_parc[5 * 8 + cpB];

        f1A = tail_step(e0A, e1A, pab5A, abp5A, P1A, P2A);
        f1B = tail_step(e0B, e1B, pab5B, abp5B, P1B, P2B);

        float qA0, qA1, qB0, qB1;
        if (ident) {
            u64 aa0 = 0ull, aa1 = 0ull, bb0 = 0ull, bb1 = 0ull;
            #pragma unroll
            for (int j = 0; j < 8; j++) {
                ulonglong2 mmA = mpA[j * 8];
                ulonglong2 mmB = mpB[j * 8];
                u64 dxA = ffma2(f1A, sA[2 * j],     mmA.x);
                u64 dyA = ffma2(f1A, sA[2 * j + 1], mmA.y);
                u64 dxB = ffma2(f1B, sB[2 * j],     mmB.x);
                u64 dyB = ffma2(f1B, sB[2 * j + 1], mmB.y);
                aa0 = ffma2(dxA, dxA, aa0); aa1 = ffma2(dyA, dyA, aa1);
                bb0 = ffma2(dxB, dxB, bb0); bb1 = ffma2(dyB, dyB, bb1);
            }
            u64 qpA = add2(aa0, aa1);
            u64 qpB = add2(bb0, bb1);
            up2(qA0, qA1, qpA);
            up2(qB0, qB1, qpB);
        } else {
            // cold path: triangular solve with Linv from GLOBAL (perf irrelevant)
            float drA0[DIMN], drA1[DIMN], drB0[DIMN], drB1[DIMN];
            #pragma unroll
            for (int j = 0; j < 8; j++) {
                ulonglong2 mmA = mpA[j * 8];
                ulonglong2 mmB = mpB[j * 8];
                u64 dxA = ffma2(f1A, sA[2 * j],     mmA.x);
                u64 dyA = ffma2(f1A, sA[2 * j + 1], mmA.y);
                u64 dxB = ffma2(f1B, sB[2 * j],     mmB.x);
                u64 dyB = ffma2(f1B, sB[2 * j + 1], mmB.y);
                up2(drA0[2 * j],     drA1[2 * j],     dxA);
                up2(drA0[2 * j + 1], drA1[2 * j + 1], dyA);
                up2(drB0[2 * j],     drB1[2 * j],     dxB);
                up2(drB0[2 * j + 1], drB1[2 * j + 1], dyB);
            }
            qA0 = qA1 = qB0 = qB1 = 0.0f;
            const float* LA0 = &g_Linv[2 * cpA * DIMN * DIMN];
            const float* LA1 = LA0 + DIMN * DIMN;
            const float* LB0 = &g_Linv[2 * cpB * DIMN * DIMN];
            const float* LB1 = LB0 + DIMN * DIMN;
            #pragma unroll 1
            for (int j = 0; j < DIMN; j++) {
                float sa0 = 0.0f, sa1 = 0.0f, sb0 = 0.0f, sb1 = 0.0f;
                #pragma unroll 1
                for (int i = 0; i <= j; i++) {
                    sa0 = fmaf(LA0[j * DIMN + i], drA0[i], sa0);
                    sa1 = fmaf(LA1[j * DIMN + i], drA1[i], sa1);
                    sb0 = fmaf(LB0[j * DIMN + i], drB0[i], sb0);
                    sb1 = fmaf(LB1[j * DIMN + i], drB1[i], sb1);
                }
                qA0 = fmaf(sa0, sa0, qA0); qA1 = fmaf(sa1, sa1, qA1);
                qB0 = fmaf(sb0, sb0, qB0); qB1 = fmaf(sb1, sb1, qB1);
            }
        }

        // log_det_jac total = log(P1^15 * P2), packed pow15; write both chains
        {
            u64 p2  = mul2(P1A, P1A);
            u64 p4  = mul2(p2, p2);
            u64 p8  = mul2(p4, p4);
            u64 g   = mul2(mul2(mul2(p8, p4), mul2(p2, P1A)), P2A);
            float g0, g1; up2(g0, g1, g);
            float h0, h1; up2(h0, h1, s_hld2[cpA]);
            float v0 = fmaf(-0.5f, qA0, -HALF_DIM_LOG2PI) - h0 + __logf(g0);
            float v1 = fmaf(-0.5f, qA1, -HALF_DIM_LOG2PI) - h1 + __logf(g1);
            if (v0 != v0) v0 = __int_as_float(0xff800000);
            if (v1 != v1) v1 = __int_as_float(0xff800000);
            *(float2*)(out + (size_t)n * CC + 2 * cpA) = make_float2(v0, v1);
        }
        {
            u64 p2  = mul2(P1B, P1B);
            u64 p4  = mul2(p2, p2);
            u64 p8  = mul2(p4, p4);
            u64 g   = mul2(mul2(mul2(p8, p4), mul2(p2, P1B)), P2B);
            float g0, g1; up2(g0, g1, g);
            float h0, h1; up2(h0, h1, s_hld2[cpB]);
            float v0 = fmaf(-0.5f, qB0, -HALF_DIM_LOG2PI) - h0 + __logf(g0);
            float v1 = fmaf(-0.5f, qB1, -HALF_DIM_LOG2PI) - h1 + __logf(g1);
            if (v0 != v0) v0 = __int_as_float(0xff800000);
            if (v1 != v1) v1 = __int_as_float(0xff800000);
            *(float2*)(out + (size_t)n * CC + 2 * cpB) = make_float2(v0, v1);
        }
    }
}

// ---------------- launch ----------------
extern "C" void kernel_launch(void* const* d_in, const int* in_sizes, int n_in,
                              void* d_out, int out_size) {
    const float* z    = (const float*)d_in[0];
    const float* z0   = (const float*)d_in[1];
    const float* la   = (const float*)d_in[2];
    const float* be   = (const float*)d_in[3];
    const float* mean = (const float*)d_in[4];
    const float* cov  = (const float*)d_in[5];
    float* out = (float*)d_out;

    int N = in_sizes[0] / DIMN;

    setup_kernel<<<1, 256>>>(la, be, z0, mean, cov);
    int blocks = (N + 127) / 128;
    density_kernel<<<blocks, 128>>>(z, out, N);
}